// round 2
// baseline (speedup 1.0000x reference)
#include <cuda_runtime.h>

#define IMW 128
#define IMH 128
#define HW 16384
#define NPTS 16384
#define NCELLS 16384
#define KNN 16
#define FDIM 64

// float32 output packing: depths | colors(HW*3) | feats(HW*64) | masks
#define OFF_DEP  0
#define OFF_COL  16384
#define OFF_FEAT 65536
#define OFF_MASK 1114112

// ---- scratch (device globals; rules forbid cudaMalloc) ----
__device__ int   g_cell_count[NCELLS];
__device__ int   g_cell_start[NCELLS + 1];
__device__ int   g_cell_cursor[NCELLS];
__device__ float g_pu[NPTS];
__device__ float g_pv[NPTS];
__device__ float g_pz[NPTS];
__device__ int   g_pid[NPTS];
__device__ float g_w[HW * KNN];
__device__ int   g_id[HW * KNN];

__device__ __forceinline__ void project_pt(const float* __restrict__ pts,
                                           const float* __restrict__ intr,
                                           int i, float& u, float& v, float& z) {
    float x = pts[3 * i + 0];
    float y = pts[3 * i + 1];
    z = pts[3 * i + 2];
    if (z > 1e-6f) {
        u = x * intr[0] / z + intr[2];   // x*fx/z + cx (same op order as reference)
        v = y * intr[4] / z + intr[5];   // y*fy/z + cy
    } else {
        u = 1e9f; v = 1e9f;              // FAR: lands in clamped edge cell, never passes d2<4
    }
}

__device__ __forceinline__ int cell_of(float u, float v) {
    int cu = (int)floorf(u);
    int cv = (int)floorf(v);
    cu = min(max(cu, 0), IMW - 1);
    cv = min(max(cv, 0), IMH - 1);
    return cv * IMW + cu;
}

__global__ void k_clear() {
    int i = blockIdx.x * blockDim.x + threadIdx.x;
    if (i < NCELLS) g_cell_count[i] = 0;
}

__global__ void k_count(const float* __restrict__ pts, const float* __restrict__ intr) {
    int i = blockIdx.x * blockDim.x + threadIdx.x;
    if (i >= NPTS) return;
    float u, v, z;
    project_pt(pts, intr, i, u, v, z);
    atomicAdd(&g_cell_count[cell_of(u, v)], 1);
}

// single-block exclusive scan over 16384 cells (1024 threads x 16 items)
__global__ void k_scan() {
    __shared__ int sh[1024];
    int t = threadIdx.x;
    int base = t * 16;
    int local[16];
    int run = 0;
#pragma unroll
    for (int i = 0; i < 16; i++) { local[i] = run; run += g_cell_count[base + i]; }
    sh[t] = run;
    __syncthreads();
    for (int off = 1; off < 1024; off <<= 1) {
        int v = (t >= off) ? sh[t - off] : 0;
        __syncthreads();
        sh[t] += v;
        __syncthreads();
    }
    int offset = (t > 0) ? sh[t - 1] : 0;
#pragma unroll
    for (int i = 0; i < 16; i++) {
        int s = offset + local[i];
        g_cell_start[base + i]  = s;
        g_cell_cursor[base + i] = s;
    }
    if (t == 1023) g_cell_start[NCELLS] = sh[1023];
}

__global__ void k_scatter(const float* __restrict__ pts, const float* __restrict__ intr) {
    int i = blockIdx.x * blockDim.x + threadIdx.x;
    if (i >= NPTS) return;
    float u, v, z;
    project_pt(pts, intr, i, u, v, z);
    int c = cell_of(u, v);
    int pos = atomicAdd(&g_cell_cursor[c], 1);
    g_pu[pos] = u;
    g_pv[pos] = v;
    g_pz[pos] = z;
    g_pid[pos] = i;
}

// 1 thread per pixel: exact top-16 by d2 among d2<4 candidates from 5x5 cells
__global__ void k_knn(const float* __restrict__ colors, float* __restrict__ out) {
    int p = blockIdx.x * blockDim.x + threadIdx.x;
    if (p >= HW) return;
    int pi = p >> 7;          // row
    int pj = p & 127;         // col
    float uc = (float)pj + 0.5f;
    float vc = (float)pi + 0.5f;

    float bd2[KNN];
    float bz[KNN];
    int   bid[KNN];
    int cnt = 0;
    float md = 0.0f; int mp = 0;   // max tracking once full

    int r0 = max(pi - 2, 0), r1 = min(pi + 2, IMH - 1);
    int c0 = max(pj - 2, 0), c1 = min(pj + 2, IMW - 1);
    for (int r = r0; r <= r1; r++) {
        int cs = g_cell_start[r * IMW + c0];
        int ce = g_cell_start[r * IMW + c1 + 1];   // cells in a row are contiguous
        for (int q = cs; q < ce; q++) {
            float du = g_pu[q] - uc;
            float dv = g_pv[q] - vc;
            float d2 = du * du + dv * dv;
            if (d2 < 4.0f) {
                if (cnt < KNN) {
                    bd2[cnt] = d2; bz[cnt] = g_pz[q]; bid[cnt] = g_pid[q];
                    cnt++;
                    if (cnt == KNN) {
                        md = bd2[0]; mp = 0;
#pragma unroll
                        for (int k = 1; k < KNN; k++)
                            if (bd2[k] > md) { md = bd2[k]; mp = k; }
                    }
                } else if (d2 < md) {
                    bd2[mp] = d2; bz[mp] = g_pz[q]; bid[mp] = g_pid[q];
                    md = bd2[0]; mp = 0;
#pragma unroll
                    for (int k = 1; k < KNN; k++)
                        if (bd2[k] > md) { md = bd2[k]; mp = k; }
                }
            }
        }
    }

    float w[KNN];
    float wsum = 0.0f;
    for (int k = 0; k < cnt; k++) { w[k] = __expf(-bd2[k]); wsum += w[k]; }
    float inv = 1.0f / (wsum + 1e-10f);

    float dep = 0.0f, col0 = 0.0f, col1 = 0.0f, col2 = 0.0f;
#pragma unroll
    for (int k = 0; k < KNN; k++) {
        float wk = (k < cnt) ? w[k] * inv : 0.0f;
        int   id = (k < cnt) ? bid[k] : 0;
        g_w[p * KNN + k]  = wk;
        g_id[p * KNN + k] = id;
        if (k < cnt) {
            dep  += bz[k] * wk;
            col0 += colors[3 * id + 0] * wk;
            col1 += colors[3 * id + 1] * wk;
            col2 += colors[3 * id + 2] * wk;
        }
    }

    out[OFF_DEP + p] = dep;
    out[OFF_COL + 3 * p + 0] = col0;
    out[OFF_COL + 3 * p + 1] = col1;
    out[OFF_COL + 3 * p + 2] = col2;
    out[OFF_MASK + p] = (cnt > 0) ? 1.0f : 0.0f;
}

// 1 warp per pixel: 64 feat dims = lane + lane+32, 16 weighted coalesced gathers
__global__ void k_feat(const float* __restrict__ feats, float* __restrict__ out) {
    int gt = blockIdx.x * blockDim.x + threadIdx.x;
    int warp = gt >> 5;
    int lane = gt & 31;
    if (warp >= HW) return;
    float a0 = 0.0f, a1 = 0.0f;
#pragma unroll
    for (int k = 0; k < KNN; k++) {
        float wk = g_w[warp * KNN + k];   // uniform broadcast across warp
        if (wk != 0.0f) {
            int id = g_id[warp * KNN + k];
            const float* row = feats + (long)id * FDIM;
            a0 += wk * row[lane];
            a1 += wk * row[lane + 32];
        }
    }
    out[OFF_FEAT + warp * FDIM + lane]      = a0;
    out[OFF_FEAT + warp * FDIM + lane + 32] = a1;
}

extern "C" void kernel_launch(void* const* d_in, const int* in_sizes, int n_in,
                              void* d_out, int out_size) {
    const float* pts    = (const float*)d_in[0];   // (N,3)
    const float* colors = (const float*)d_in[1];   // (N,3)
    const float* feats  = (const float*)d_in[2];   // (N,64)
    const float* intr   = (const float*)d_in[3];   // (3,3)
    float* out = (float*)d_out;

    k_clear  <<<NCELLS / 256, 256>>>();
    k_count  <<<NPTS / 256, 256>>>(pts, intr);
    k_scan   <<<1, 1024>>>();
    k_scatter<<<NPTS / 256, 256>>>(pts, intr);
    k_knn    <<<HW / 128, 128>>>(colors, out);
    k_feat   <<<(HW * 32) / 256, 256>>>(feats, out);
}

// round 5
// speedup vs baseline: 1.6963x; 1.6963x over previous
#include <cuda_runtime.h>

#define IMW 128
#define IMH 128
#define HW 16384
#define NPTS 16384
#define NCELLS 16384
#define KNN 16
#define FDIM 64
#define CAP 24          // bin capacity per cell (Poisson(1) occupancy; P(>24) ~ 1e-24)
#define CSLOT 3         // candidate slots per lane (covers 96 scanned candidates)

// float32 output packing: depths | colors(HW*3) | feats(HW*64) | masks
#define OFF_DEP  0
#define OFF_COL  16384
#define OFF_FEAT 65536
#define OFF_MASK 1114112

#define FULL 0xFFFFFFFFu
#define KEY_INF 0xFFFFFFFFFFFFFFFFull

// ---- scratch (device globals; no cudaMalloc allowed) ----
__device__ int    g_cnt[NCELLS];
__device__ float4 g_bin[NCELLS * CAP];

__global__ void k_clear() {
    int i = blockIdx.x * blockDim.x + threadIdx.x;
    if (i < NCELLS) g_cnt[i] = 0;
}

__global__ void k_bin(const float* __restrict__ pts, const float* __restrict__ intr) {
    int i = blockIdx.x * blockDim.x + threadIdx.x;
    if (i >= NPTS) return;
    float x = pts[3 * i + 0];
    float y = pts[3 * i + 1];
    float z = pts[3 * i + 2];
    if (z <= 1e-6f) return;                    // FAR point: pix=1e9, never within radius
    float u = x * intr[0] / z + intr[2];       // same op order as reference
    float v = y * intr[4] / z + intr[5];
    int cu = min(max((int)floorf(u), 0), IMW - 1);
    int cv = min(max((int)floorf(v), 0), IMH - 1);
    int c = cv * IMW + cu;
    int pos = atomicAdd(&g_cnt[c], 1);
    if (pos < CAP) g_bin[c * CAP + pos] = make_float4(u, v, z, __int_as_float(i));
}

// 1 warp per pixel: exact top-16 (by d2, among d2<4) via iterative warp min-extraction.
// Fuses depth + color + 64-dim feature accumulation + mask.
__global__ void __launch_bounds__(256)
k_main(const float* __restrict__ colors, const float* __restrict__ feats,
       float* __restrict__ out) {
    __shared__ int s_pre[8][32];
    __shared__ int s_base[8][32];

    int gt = blockIdx.x * blockDim.x + threadIdx.x;
    int p = gt >> 5;
    int lane = gt & 31;
    int w8 = (threadIdx.x >> 5);
    if (p >= HW) return;

    int pi = p >> 7, pj = p & 127;
    float uc = (float)pj + 0.5f;
    float vc = (float)pi + 0.5f;

    int r0 = max(pi - 2, 0), r1 = min(pi + 2, IMH - 1);
    int c0 = max(pj - 2, 0), c1 = min(pj + 2, IMW - 1);
    int wdt = c1 - c0 + 1;
    int nseg = (r1 - r0 + 1) * wdt;

    // per-lane segment count + base
    int cnt_l = 0, base_l = 0;
    if (lane < nseg) {
        int cell = (r0 + lane / wdt) * IMW + (c0 + lane % wdt);
        cnt_l = min(g_cnt[cell], CAP);
        base_l = cell * CAP;
    }
    // inclusive warp scan of counts
    int pre = cnt_l;
#pragma unroll
    for (int off = 1; off < 32; off <<= 1) {
        int o = __shfl_up_sync(FULL, pre, off);
        if (lane >= off) pre += o;
    }
    int T = __shfl_sync(FULL, pre, 31);

    s_pre[w8][lane]  = pre;
    s_base[w8][lane] = base_l;
    __syncwarp();

    // gather candidate slots into registers
    unsigned long long key[CSLOT];
    float zs[CSLOT];
    int   ids[CSLOT];
#pragma unroll
    for (int s = 0; s < CSLOT; s++) {
        key[s] = KEY_INF; zs[s] = 0.0f; ids[s] = 0;
        int g = lane + 32 * s;
        if (g < T) {
            // binary search: sidx = #{i : pre[i] <= g}
            int sidx = 0;
#pragma unroll
            for (int st = 16; st >= 1; st >>= 1) {
                int t = sidx + st - 1;
                if (t < 32 && s_pre[w8][t] <= g) sidx += st;
            }
            int excl = (sidx > 0) ? s_pre[w8][sidx - 1] : 0;
            float4 pt = g_bin[s_base[w8][sidx] + (g - excl)];
            float du = pt.x - uc;
            float dv = pt.y - vc;
            float d2 = du * du + dv * dv;
            if (d2 < 4.0f) {
                key[s] = (((unsigned long long)__float_as_uint(d2)) << 32)
                       | (unsigned long long)((lane << 2) | s);
                zs[s]  = pt.z;
                ids[s] = __float_as_int(pt.w);
            }
        }
    }

    // iterative extraction of 16 smallest d2
    float wsum = 0.0f, dep = 0.0f, col = 0.0f, a0 = 0.0f, a1 = 0.0f;
    int cnt = 0;
#pragma unroll 1
    for (int k = 0; k < KNN; k++) {
        unsigned long long m = key[0];
#pragma unroll
        for (int s = 1; s < CSLOT; s++) m = min(m, key[s]);
#pragma unroll
        for (int off = 16; off >= 1; off >>= 1)
            m = min(m, __shfl_xor_sync(FULL, m, off));
        if (m == KEY_INF) break;

        float d2 = __uint_as_float((unsigned)(m >> 32));
        int src  = (int)(m & 0x7F);
        int L = src >> 2, s = src & 3;

        float wk = __expf(-d2);
        float zsel = (s == 0) ? zs[0] : ((s == 1) ? zs[1] : zs[2]);
        int   isel = (s == 0) ? ids[0] : ((s == 1) ? ids[1] : ids[2]);
        float zk = __shfl_sync(FULL, zsel, L);
        int   id = __shfl_sync(FULL, isel, L);
        if (lane == L) {
            if (s == 0) key[0] = KEY_INF;
            else if (s == 1) key[1] = KEY_INF;
            else key[2] = KEY_INF;
        }

        wsum += wk;
        dep  += wk * zk;
        if (lane < 3) col += wk * colors[3 * id + lane];
        const float* row = feats + (long)id * FDIM;
        a0 += wk * row[lane];
        a1 += wk * row[lane + 32];
        cnt++;
    }

    float inv = 1.0f / (wsum + 1e-10f);
    if (lane == 0) {
        out[OFF_DEP + p]  = dep * inv;
        out[OFF_MASK + p] = (cnt > 0) ? 1.0f : 0.0f;
    }
    if (lane < 3) out[OFF_COL + 3 * p + lane] = col * inv;
    out[OFF_FEAT + p * FDIM + lane]      = a0 * inv;
    out[OFF_FEAT + p * FDIM + lane + 32] = a1 * inv;
}

extern "C" void kernel_launch(void* const* d_in, const int* in_sizes, int n_in,
                              void* d_out, int out_size) {
    const float* pts    = (const float*)d_in[0];   // (N,3)
    const float* colors = (const float*)d_in[1];   // (N,3)
    const float* feats  = (const float*)d_in[2];   // (N,64)
    const float* intr   = (const float*)d_in[3];   // (3,3)
    float* out = (float*)d_out;

    k_clear<<<NCELLS / 256, 256>>>();
    k_bin  <<<NPTS / 256, 256>>>(pts, intr);
    k_main <<<(HW * 32) / 256, 256>>>(colors, feats, out);
}

// round 6
// speedup vs baseline: 2.0720x; 1.2215x over previous
#include <cuda_runtime.h>

#define IMW 128
#define IMH 128
#define HW 16384
#define NPTS 16384
#define NCELLS 16384
#define KNN 16
#define FDIM 64
#define CAP 24          // bin capacity per cell (Poisson(1); P(>24) ~ 1e-24)
#define CSLOT 3         // candidate slots per lane (96 max candidates, Poisson(~21) tail ~0)
#define NOFF 21         // 5x5 window minus 4 corner cells (min d2 = 4.5 > 4)

// float32 output packing: depths | colors(HW*3) | feats(HW*64) | masks
#define OFF_DEP  0
#define OFF_COL  16384
#define OFF_FEAT 65536
#define OFF_MASK 1114112

#define FULL 0xFFFFFFFFu
#define KEY_INF 0xFFFFFFFFFFFFFFFFull

// ---- scratch (device globals; no cudaMalloc allowed) ----
__device__ int    g_cnt[NCELLS];
__device__ float4 g_bin[NCELLS * CAP];

// relative (dr,dc) offsets of the 21 reachable cells
__constant__ signed char c_off[NOFF][2] = {
            {-2,-1},{-2,0},{-2,1},
    {-1,-2},{-1,-1},{-1,0},{-1,1},{-1,2},
    { 0,-2},{ 0,-1},{ 0,0},{ 0,1},{ 0,2},
    { 1,-2},{ 1,-1},{ 1,0},{ 1,1},{ 1,2},
            { 2,-1},{ 2,0},{ 2,1}
};

__global__ void k_bin(const float* __restrict__ pts, const float* __restrict__ intr) {
    int i = blockIdx.x * blockDim.x + threadIdx.x;
    if (i >= NPTS) return;
    float x = pts[3 * i + 0];
    float y = pts[3 * i + 1];
    float z = pts[3 * i + 2];
    if (z <= 1e-6f) return;                    // FAR point: never within radius
    float u = x * intr[0] / z + intr[2];       // same op order as reference
    float v = y * intr[4] / z + intr[5];
    int cu = min(max((int)floorf(u), 0), IMW - 1);
    int cv = min(max((int)floorf(v), 0), IMH - 1);
    int c = cv * IMW + cu;
    int pos = atomicAdd(&g_cnt[c], 1);
    if (pos < CAP) g_bin[c * CAP + pos] = make_float4(u, v, z, __int_as_float(i));
}

// 1 warp per pixel. Fast path (<=16 in-radius): order-free accumulation via ballot/ffs.
// Slow path (>16): exact top-16 by iterative u64 warp min-extraction.
__global__ void __launch_bounds__(256)
k_main(const float* __restrict__ colors, const float* __restrict__ feats,
       float* __restrict__ out) {
    __shared__ int s_pre[8][32];
    __shared__ int s_base[8][32];

    int gt = blockIdx.x * blockDim.x + threadIdx.x;
    int p = gt >> 5;
    int lane = gt & 31;
    int w8 = (threadIdx.x >> 5);
    if (p >= HW) return;

    int pi = p >> 7, pj = p & 127;
    float uc = (float)pj + 0.5f;
    float vc = (float)pi + 0.5f;

    // per-lane cell (21 reachable offsets)
    int cnt_l = 0, base_l = 0;
    if (lane < NOFF) {
        int r = pi + c_off[lane][0];
        int c = pj + c_off[lane][1];
        if (r >= 0 && r < IMH && c >= 0 && c < IMW) {
            int cell = r * IMW + c;
            cnt_l = min(g_cnt[cell], CAP);
            base_l = cell * CAP;
        }
    }
    // inclusive warp scan of counts
    int pre = cnt_l;
#pragma unroll
    for (int off = 1; off < 32; off <<= 1) {
        int o = __shfl_up_sync(FULL, pre, off);
        if (lane >= off) pre += o;
    }
    int T = __shfl_sync(FULL, pre, 31);

    s_pre[w8][lane]  = pre;
    s_base[w8][lane] = base_l;
    __syncwarp();

    // gather candidates into register slots
    float d2s[CSLOT], zsl[CSLOT];
    int   ids[CSLOT];
    bool  val[CSLOT];
#pragma unroll
    for (int s = 0; s < CSLOT; s++) {
        d2s[s] = 0.0f; zsl[s] = 0.0f; ids[s] = 0; val[s] = false;
        int g = lane + 32 * s;
        if (g < T) {
            int sidx = 0;
#pragma unroll
            for (int st = 16; st >= 1; st >>= 1) {
                int t = sidx + st - 1;
                if (t < 32 && s_pre[w8][t] <= g) sidx += st;
            }
            int excl = (sidx > 0) ? s_pre[w8][sidx - 1] : 0;
            float4 pt = g_bin[s_base[w8][sidx] + (g - excl)];
            float du = pt.x - uc;
            float dv = pt.y - vc;
            float d2 = du * du + dv * dv;
            if (d2 < 4.0f) {
                val[s] = true;
                d2s[s] = d2;
                zsl[s] = pt.z;
                ids[s] = __float_as_int(pt.w);
            }
        }
    }

    unsigned bal[CSLOT];
    int nval = 0;
#pragma unroll
    for (int s = 0; s < CSLOT; s++) { bal[s] = __ballot_sync(FULL, val[s]); nval += __popc(bal[s]); }

    float wsum = 0.0f, dep = 0.0f, col = 0.0f, a0 = 0.0f, a1 = 0.0f;
    int cnt = 0;

    if (nval <= KNN) {
        // ---- fast path: no selection needed, sum all in-radius candidates ----
#pragma unroll
        for (int s = 0; s < CSLOT; s++) {
            unsigned m = bal[s];
            while (m) {
                int L = __ffs(m) - 1;
                m &= m - 1;
                float d2 = __shfl_sync(FULL, d2s[s], L);
                float zk = __shfl_sync(FULL, zsl[s], L);
                int   id = __shfl_sync(FULL, ids[s], L);
                float wk = __expf(-d2);
                wsum += wk;
                dep  += wk * zk;
                if (lane < 3) col += wk * colors[3 * id + lane];
                const float* row = feats + (long)id * FDIM;
                a0 += wk * row[lane];
                a1 += wk * row[lane + 32];
            }
        }
        cnt = nval;
    } else {
        // ---- slow path: exact top-16 via iterative warp min-extraction ----
        unsigned long long key[CSLOT];
#pragma unroll
        for (int s = 0; s < CSLOT; s++)
            key[s] = val[s]
                ? ((((unsigned long long)__float_as_uint(d2s[s])) << 32)
                   | (unsigned long long)((lane << 2) | s))
                : KEY_INF;

#pragma unroll 1
        for (int k = 0; k < KNN; k++) {
            unsigned long long mkey = key[0];
#pragma unroll
            for (int s = 1; s < CSLOT; s++) mkey = min(mkey, key[s]);
#pragma unroll
            for (int off = 16; off >= 1; off >>= 1)
                mkey = min(mkey, __shfl_xor_sync(FULL, mkey, off));

            float d2 = __uint_as_float((unsigned)(mkey >> 32));
            int src  = (int)(mkey & 0x7F);
            int L = src >> 2, s = src & 3;

            float zsel = (s == 0) ? zsl[0] : ((s == 1) ? zsl[1] : zsl[2]);
            int   isel = (s == 0) ? ids[0] : ((s == 1) ? ids[1] : ids[2]);
            float zk = __shfl_sync(FULL, zsel, L);
            int   id = __shfl_sync(FULL, isel, L);
            if (lane == L) {
                if (s == 0) key[0] = KEY_INF;
                else if (s == 1) key[1] = KEY_INF;
                else key[2] = KEY_INF;
            }

            float wk = __expf(-d2);
            wsum += wk;
            dep  += wk * zk;
            if (lane < 3) col += wk * colors[3 * id + lane];
            const float* row = feats + (long)id * FDIM;
            a0 += wk * row[lane];
            a1 += wk * row[lane + 32];
        }
        cnt = KNN;
    }

    float inv = 1.0f / (wsum + 1e-10f);
    if (lane == 0) {
        out[OFF_DEP + p]  = dep * inv;
        out[OFF_MASK + p] = (cnt > 0) ? 1.0f : 0.0f;
    }
    if (lane < 3) out[OFF_COL + 3 * p + lane] = col * inv;
    out[OFF_FEAT + p * FDIM + lane]      = a0 * inv;
    out[OFF_FEAT + p * FDIM + lane + 32] = a1 * inv;
}

extern "C" void kernel_launch(void* const* d_in, const int* in_sizes, int n_in,
                              void* d_out, int out_size) {
    const float* pts    = (const float*)d_in[0];   // (N,3)
    const float* colors = (const float*)d_in[1];   // (N,3)
    const float* feats  = (const float*)d_in[2];   // (N,64)
    const float* intr   = (const float*)d_in[3];   // (3,3)
    float* out = (float*)d_out;

    void* cnt_addr = nullptr;
    cudaGetSymbolAddress(&cnt_addr, g_cnt);
    cudaMemsetAsync(cnt_addr, 0, NCELLS * sizeof(int), 0);  // replaces k_clear kernel

    k_bin  <<<NPTS / 128, 128>>>(pts, intr);
    k_main <<<(HW * 32) / 256, 256>>>(colors, feats, out);
}

// round 7
// speedup vs baseline: 2.2064x; 1.0649x over previous
#include <cuda_runtime.h>

#define IMW 128
#define IMH 128
#define HW 16384
#define NPTS 16384
#define NCELLS 16384
#define KNN 16
#define FDIM 64
#define CAP 24          // bin capacity per cell (Poisson(1); P(>24) ~ 1e-24)
#define CSLOT 3         // candidate slots per lane (96 max scanned; P(>96) ~ 0)
#define NOFF 21         // 5x5 window minus 4 corners (min d2 = 4.5 > 4)

// float32 output packing: depths | colors(HW*3) | feats(HW*64) | masks
#define OFF_DEP  0
#define OFF_COL  16384
#define OFF_FEAT 65536
#define OFF_MASK 1114112

#define FULL 0xFFFFFFFFu
#define KEY_INF 0xFFFFFFFFFFFFFFFFull

// ---- scratch (device globals; no cudaMalloc allowed) ----
__device__ int    g_cnt[NCELLS];
__device__ float4 g_bin[NCELLS * CAP];

// relative (dr,dc) offsets of the 21 reachable cells
__constant__ signed char c_off[NOFF][2] = {
            {-2,-1},{-2,0},{-2,1},
    {-1,-2},{-1,-1},{-1,0},{-1,1},{-1,2},
    { 0,-2},{ 0,-1},{ 0,0},{ 0,1},{ 0,2},
    { 1,-2},{ 1,-1},{ 1,0},{ 1,1},{ 1,2},
            { 2,-1},{ 2,0},{ 2,1}
};

__global__ void k_bin(const float* __restrict__ pts, const float* __restrict__ intr) {
    int i = blockIdx.x * blockDim.x + threadIdx.x;
    if (i >= NPTS) return;
    float x = pts[3 * i + 0];
    float y = pts[3 * i + 1];
    float z = pts[3 * i + 2];
    if (z <= 1e-6f) return;                    // FAR point: never within radius
    float u = x * intr[0] / z + intr[2];       // same op order as reference
    float v = y * intr[4] / z + intr[5];
    int cu = min(max((int)floorf(u), 0), IMW - 1);
    int cv = min(max((int)floorf(v), 0), IMH - 1);
    int c = cv * IMW + cu;
    int pos = atomicAdd(&g_cnt[c], 1);
    if (pos < CAP) g_bin[c * CAP + pos] = make_float4(u, v, z, __int_as_float(i));
}

// 1 warp per pixel. Selected (wk,id) compacted to smem, then a pipelined
// broadcast-load accumulation loop (independent iterations -> MLP).
__global__ void __launch_bounds__(256)
k_main(const float* __restrict__ colors, const float* __restrict__ feats,
       float* __restrict__ out) {
    __shared__ int   s_pre[8][32];
    __shared__ int   s_base[8][32];
    __shared__ float s_wk[8][KNN];
    __shared__ int   s_id[8][KNN];

    int gt = blockIdx.x * blockDim.x + threadIdx.x;
    int p = gt >> 5;
    int lane = gt & 31;
    int w8 = (threadIdx.x >> 5);
    if (p >= HW) return;

    int pi = p >> 7, pj = p & 127;
    float uc = (float)pj + 0.5f;
    float vc = (float)pi + 0.5f;

    // per-lane cell (21 reachable offsets)
    int cnt_l = 0, base_l = 0;
    if (lane < NOFF) {
        int r = pi + c_off[lane][0];
        int c = pj + c_off[lane][1];
        if (r >= 0 && r < IMH && c >= 0 && c < IMW) {
            int cell = r * IMW + c;
            cnt_l = min(g_cnt[cell], CAP);
            base_l = cell * CAP;
        }
    }
    // inclusive warp scan of counts
    int pre = cnt_l;
#pragma unroll
    for (int off = 1; off < 32; off <<= 1) {
        int o = __shfl_up_sync(FULL, pre, off);
        if (lane >= off) pre += o;
    }
    int T = __shfl_sync(FULL, pre, 31);

    s_pre[w8][lane]  = pre;
    s_base[w8][lane] = base_l;
    __syncwarp();

    // gather candidates into register slots; expf computed by OWNER lane only
    float wks[CSLOT], zsl[CSLOT], d2s[CSLOT];
    int   ids[CSLOT];
    bool  val[CSLOT];
#pragma unroll
    for (int s = 0; s < CSLOT; s++) {
        wks[s] = 0.0f; zsl[s] = 0.0f; d2s[s] = 0.0f; ids[s] = 0; val[s] = false;
        int g = lane + 32 * s;
        if (g < T) {
            int sidx = 0;
#pragma unroll
            for (int st = 16; st >= 1; st >>= 1) {
                int t = sidx + st - 1;
                if (t < 32 && s_pre[w8][t] <= g) sidx += st;
            }
            int excl = (sidx > 0) ? s_pre[w8][sidx - 1] : 0;
            float4 pt = g_bin[s_base[w8][sidx] + (g - excl)];
            float du = pt.x - uc;
            float dv = pt.y - vc;
            float d2 = du * du + dv * dv;
            if (d2 < 4.0f) {
                val[s] = true;
                d2s[s] = d2;
                wks[s] = __expf(-d2);
                zsl[s] = pt.z;
                ids[s] = __float_as_int(pt.w);
            }
        }
    }

    unsigned bal[CSLOT];
    int nval = 0;
#pragma unroll
    for (int s = 0; s < CSLOT; s++) { bal[s] = __ballot_sync(FULL, val[s]); nval += __popc(bal[s]); }

    float wsum, dep;
    int cnt;
    unsigned lt = (1u << lane) - 1u;

    if (nval <= KNN) {
        // ---- fast path: compact all valid candidates via ballot rank ----
        int b0 = __popc(bal[0]);
        int b1 = b0 + __popc(bal[1]);
#pragma unroll
        for (int s = 0; s < CSLOT; s++) {
            if (val[s]) {
                int rk = ((s == 0) ? 0 : (s == 1) ? b0 : b1) + __popc(bal[s] & lt);
                s_wk[w8][rk] = wks[s];
                s_id[w8][rk] = ids[s];
            }
        }
        // per-lane partial wsum / depth, butterfly reduce
        float lsum = 0.0f, ldep = 0.0f;
#pragma unroll
        for (int s = 0; s < CSLOT; s++) { lsum += wks[s]; ldep += wks[s] * zsl[s]; }
#pragma unroll
        for (int off = 16; off >= 1; off >>= 1) {
            lsum += __shfl_xor_sync(FULL, lsum, off);
            ldep += __shfl_xor_sync(FULL, ldep, off);
        }
        wsum = lsum; dep = ldep; cnt = nval;
        __syncwarp();
    } else {
        // ---- slow path: exact top-16 via iterative warp min-extraction ----
        unsigned long long key[CSLOT];
#pragma unroll
        for (int s = 0; s < CSLOT; s++)
            key[s] = val[s]
                ? ((((unsigned long long)__float_as_uint(d2s[s])) << 32)
                   | (unsigned long long)((lane << 2) | s))
                : KEY_INF;

        wsum = 0.0f; dep = 0.0f;
#pragma unroll 1
        for (int k = 0; k < KNN; k++) {
            unsigned long long mkey = key[0];
#pragma unroll
            for (int s = 1; s < CSLOT; s++) mkey = min(mkey, key[s]);
#pragma unroll
            for (int off = 16; off >= 1; off >>= 1)
                mkey = min(mkey, __shfl_xor_sync(FULL, mkey, off));

            float d2 = __uint_as_float((unsigned)(mkey >> 32));
            int src  = (int)(mkey & 0x7F);
            int L = src >> 2, s = src & 3;

            float zsel = (s == 0) ? zsl[0] : ((s == 1) ? zsl[1] : zsl[2]);
            int   isel = (s == 0) ? ids[0] : ((s == 1) ? ids[1] : ids[2]);
            float zk = __shfl_sync(FULL, zsel, L);
            int   id = __shfl_sync(FULL, isel, L);
            if (lane == L) {
                if (s == 0) key[0] = KEY_INF;
                else if (s == 1) key[1] = KEY_INF;
                else key[2] = KEY_INF;
            }

            float wk = __expf(-d2);
            wsum += wk;
            dep  += wk * zk;
            if (lane == 0) { s_wk[w8][k] = wk; s_id[w8][k] = id; }
        }
        cnt = KNN;
        __syncwarp();
    }

    // ---- shared accumulation loop: independent iterations, coalesced LDGs ----
    float col = 0.0f, a0 = 0.0f, a1 = 0.0f;
#pragma unroll 4
    for (int k = 0; k < cnt; k++) {
        float wk = s_wk[w8][k];           // LDS broadcast (conflict-free)
        int   id = s_id[w8][k];
        const float* row = feats + (long)id * FDIM;
        a0 += wk * row[lane];
        a1 += wk * row[lane + 32];
        if (lane < 3) col += wk * colors[3 * id + lane];
    }

    float inv = 1.0f / (wsum + 1e-10f);
    if (lane == 0) {
        out[OFF_DEP + p]  = dep * inv;
        out[OFF_MASK + p] = (cnt > 0) ? 1.0f : 0.0f;
    }
    if (lane < 3) out[OFF_COL + 3 * p + lane] = col * inv;
    out[OFF_FEAT + p * FDIM + lane]      = a0 * inv;
    out[OFF_FEAT + p * FDIM + lane + 32] = a1 * inv;
}

extern "C" void kernel_launch(void* const* d_in, const int* in_sizes, int n_in,
                              void* d_out, int out_size) {
    const float* pts    = (const float*)d_in[0];   // (N,3)
    const float* colors = (const float*)d_in[1];   // (N,3)
    const float* feats  = (const float*)d_in[2];   // (N,64)
    const float* intr   = (const float*)d_in[3];   // (3,3)
    float* out = (float*)d_out;

    void* cnt_addr = nullptr;
    cudaGetSymbolAddress(&cnt_addr, g_cnt);
    cudaMemsetAsync(cnt_addr, 0, NCELLS * sizeof(int), 0);

    k_bin  <<<NPTS / 128, 128>>>(pts, intr);
    k_main <<<(HW * 32) / 256, 256>>>(colors, feats, out);
}

// round 8
// speedup vs baseline: 2.3834x; 1.0803x over previous
#include <cuda_runtime.h>

#define IMW 128
#define IMH 128
#define HW 16384
#define NPTS 16384
#define NCELLS 16384
#define KNN 16
#define FDIM 64
#define CAP 24          // bin capacity per cell (Poisson(1); P(>24) ~ 1e-24)
#define NOFF 21         // 5x5 window minus 4 corners (min d2 = 4.5 > 4)
#define MAXC 48         // max in-radius candidates kept (Poisson(12.6); P(>48) ~ 1e-13)

// float32 output packing: depths | colors(HW*3) | feats(HW*64) | masks
#define OFF_DEP  0
#define OFF_COL  16384
#define OFF_FEAT 65536
#define OFF_MASK 1114112

#define FULL 0xFFFFFFFFu

// ---- scratch (device globals; no cudaMalloc allowed) ----
__device__ int    g_cnt[NCELLS];
__device__ float4 g_bin[NCELLS * CAP];

// relative (dr,dc) offsets of the 21 reachable cells
__constant__ signed char c_off[NOFF][2] = {
            {-2,-1},{-2,0},{-2,1},
    {-1,-2},{-1,-1},{-1,0},{-1,1},{-1,2},
    { 0,-2},{ 0,-1},{ 0,0},{ 0,1},{ 0,2},
    { 1,-2},{ 1,-1},{ 1,0},{ 1,1},{ 1,2},
            { 2,-1},{ 2,0},{ 2,1}
};

__global__ void k_bin(const float* __restrict__ pts, const float* __restrict__ intr) {
    int i = blockIdx.x * blockDim.x + threadIdx.x;
    if (i >= NPTS) return;
    float x = pts[3 * i + 0];
    float y = pts[3 * i + 1];
    float z = pts[3 * i + 2];
    if (z <= 1e-6f) return;                    // FAR point: never within radius
    float u = x * intr[0] / z + intr[2];       // same op order as reference
    float v = y * intr[4] / z + intr[5];
    int cu = min(max((int)floorf(u), 0), IMW - 1);
    int cv = min(max((int)floorf(v), 0), IMH - 1);
    int c = cv * IMW + cu;
    int pos = atomicAdd(&g_cnt[c], 1);
    if (pos < CAP) g_bin[c * CAP + pos] = make_float4(u, v, z, __int_as_float(i));
}

// 1 warp per pixel. Lane l walks cell l of the 21-cell window directly
// (no scan / binary search). Survivors ballot-compacted into smem.
// >16 in-radius: parallel rank-selection over the compacted list.
__global__ void __launch_bounds__(256)
k_main(const float* __restrict__ colors, const float* __restrict__ feats,
       float* __restrict__ out) {
    __shared__ float s_d2[8][MAXC];
    __shared__ float s_wk[8][MAXC];
    __shared__ float s_z [8][MAXC];
    __shared__ int   s_id[8][MAXC];

    int gt = blockIdx.x * blockDim.x + threadIdx.x;
    int p = gt >> 5;
    int lane = gt & 31;
    int w8 = (threadIdx.x >> 5);
    if (p >= HW) return;

    int pi = p >> 7, pj = p & 127;
    float uc = (float)pj + 0.5f;
    float vc = (float)pi + 0.5f;
    unsigned lt = (1u << lane) - 1u;

    // lane -> cell mapping
    int cnt_l = 0, base_l = 0;
    if (lane < NOFF) {
        int r = pi + c_off[lane][0];
        int c = pj + c_off[lane][1];
        if (r >= 0 && r < IMH && c >= 0 && c < IMW) {
            int cell = r * IMW + c;
            cnt_l = min(g_cnt[cell], CAP);
            base_l = cell * CAP;
        }
    }
    // warp max cell occupancy = loop bound
    int maxc = cnt_l;
#pragma unroll
    for (int off = 16; off >= 1; off >>= 1)
        maxc = max(maxc, __shfl_xor_sync(FULL, maxc, off));

    // walk own cell; compact in-radius candidates into smem via ballot rank
    int nval = 0;
    float lsum = 0.0f, ldep = 0.0f;     // fast-path partials
#pragma unroll 1
    for (int j = 0; j < maxc; j++) {
        bool valid = false;
        float d2 = 0.0f, wk = 0.0f, z = 0.0f;
        int id = 0;
        if (j < cnt_l) {
            float4 pt = g_bin[base_l + j];
            float du = pt.x - uc;
            float dv = pt.y - vc;
            d2 = du * du + dv * dv;
            if (d2 < 4.0f) {
                valid = true;
                wk = __expf(-d2);
                z  = pt.z;
                id = __float_as_int(pt.w);
            }
        }
        unsigned bal = __ballot_sync(FULL, valid);
        int rk = nval + __popc(bal & lt);
        if (valid && rk < MAXC) {
            s_d2[w8][rk] = d2;
            s_wk[w8][rk] = wk;
            s_z [w8][rk] = z;
            s_id[w8][rk] = id;
            lsum += wk;
            ldep += wk * z;
        }
        nval += __popc(bal);
    }
    nval = min(nval, MAXC);
    __syncwarp();

    float wsum, dep;
    int cnt;

    if (nval <= KNN) {
        // ---- fast path: all candidates contribute; reduce register partials ----
#pragma unroll
        for (int off = 16; off >= 1; off >>= 1) {
            lsum += __shfl_xor_sync(FULL, lsum, off);
            ldep += __shfl_xor_sync(FULL, ldep, off);
        }
        wsum = lsum; dep = ldep; cnt = nval;
    } else {
        // ---- slow path: parallel rank selection of 16 smallest d2 ----
        bool own0 = lane < nval;
        bool own1 = lane + 32 < nval;
        float d20 = own0 ? s_d2[w8][lane] : 0.0f;
        float d21 = own1 ? s_d2[w8][lane + 32] : 0.0f;
        float wk0 = own0 ? s_wk[w8][lane] : 0.0f;
        float wk1 = own1 ? s_wk[w8][lane + 32] : 0.0f;
        float z0  = own0 ? s_z [w8][lane] : 0.0f;
        float z1  = own1 ? s_z [w8][lane + 32] : 0.0f;
        int   id0 = own0 ? s_id[w8][lane] : 0;
        int   id1 = own1 ? s_id[w8][lane + 32] : 0;

        int r0 = 0, r1 = 0;
#pragma unroll 4
        for (int j = 0; j < nval; j++) {
            float dj = s_d2[w8][j];       // LDS broadcast, conflict-free
            r0 += (dj < d20) || (dj == d20 && j < lane);
            r1 += (dj < d21) || (dj == d21 && j < lane + 32);
        }
        bool sel0 = own0 && r0 < KNN;
        bool sel1 = own1 && r1 < KNN;

        float ls = 0.0f, ld = 0.0f;
        if (sel0) { ls += wk0; ld += wk0 * z0; }
        if (sel1) { ls += wk1; ld += wk1 * z1; }
#pragma unroll
        for (int off = 16; off >= 1; off >>= 1) {
            ls += __shfl_xor_sync(FULL, ls, off);
            ld += __shfl_xor_sync(FULL, ld, off);
        }
        wsum = ls; dep = ld;

        // compact the 16 selected (wk,id) to the front for the accumulation loop
        unsigned b0 = __ballot_sync(FULL, sel0);
        unsigned b1 = __ballot_sync(FULL, sel1);
        __syncwarp();                     // reads above complete before overwrite
        if (sel0) {
            int rk = __popc(b0 & lt);
            s_wk[w8][rk] = wk0; s_id[w8][rk] = id0;
        }
        if (sel1) {
            int rk = __popc(b0) + __popc(b1 & lt);
            s_wk[w8][rk] = wk1; s_id[w8][rk] = id1;
        }
        cnt = KNN;
        __syncwarp();
    }

    // ---- accumulation: independent iterations, coalesced feat LDGs ----
    float col = 0.0f, a0 = 0.0f, a1 = 0.0f;
#pragma unroll 4
    for (int k = 0; k < cnt; k++) {
        float wk = s_wk[w8][k];           // LDS broadcast
        int   id = s_id[w8][k];
        const float* row = feats + (long)id * FDIM;
        a0 += wk * row[lane];
        a1 += wk * row[lane + 32];
        if (lane < 3) col += wk * colors[3 * id + lane];
    }

    float inv = 1.0f / (wsum + 1e-10f);
    if (lane == 0) {
        out[OFF_DEP + p]  = dep * inv;
        out[OFF_MASK + p] = (cnt > 0) ? 1.0f : 0.0f;
    }
    if (lane < 3) out[OFF_COL + 3 * p + lane] = col * inv;
    out[OFF_FEAT + p * FDIM + lane]      = a0 * inv;
    out[OFF_FEAT + p * FDIM + lane + 32] = a1 * inv;
}

extern "C" void kernel_launch(void* const* d_in, const int* in_sizes, int n_in,
                              void* d_out, int out_size) {
    const float* pts    = (const float*)d_in[0];   // (N,3)
    const float* colors = (const float*)d_in[1];   // (N,3)
    const float* feats  = (const float*)d_in[2];   // (N,64)
    const float* intr   = (const float*)d_in[3];   // (3,3)
    float* out = (float*)d_out;

    void* cnt_addr = nullptr;
    cudaGetSymbolAddress(&cnt_addr, g_cnt);
    cudaMemsetAsync(cnt_addr, 0, NCELLS * sizeof(int), 0);

    k_bin  <<<NPTS / 128, 128>>>(pts, intr);
    k_main <<<(HW * 32) / 256, 256>>>(colors, feats, out);
}

// round 9
// speedup vs baseline: 2.5986x; 1.0903x over previous
#include <cuda_runtime.h>

#define IMW 128
#define IMH 128
#define HW 16384
#define NPTS 16384
#define NCELLS 16384
#define KNN 16
#define FDIM 64
#define CAP 24          // bin capacity per cell (Poisson(1); P(>24) ~ 1e-24)
#define NOFF 21         // 5x5 window minus 4 corners (min d2 = 4.5 > 4)
#define MAXC 48         // max in-radius candidates kept (Poisson(12.6); P(>48) ~ 1e-13)

// float32 output packing: depths | colors(HW*3) | feats(HW*64) | masks
#define OFF_DEP  0
#define OFF_COL  16384
#define OFF_FEAT 65536
#define OFF_MASK 1114112

#define FULL 0xFFFFFFFFu

// ---- scratch (device globals; no cudaMalloc allowed) ----
__device__ int    g_cnt[NCELLS];
__device__ float4 g_bin[NCELLS * CAP];

// relative (dr,dc) offsets of the 21 reachable cells
__constant__ signed char c_off[NOFF][2] = {
            {-2,-1},{-2,0},{-2,1},
    {-1,-2},{-1,-1},{-1,0},{-1,1},{-1,2},
    { 0,-2},{ 0,-1},{ 0,0},{ 0,1},{ 0,2},
    { 1,-2},{ 1,-1},{ 1,0},{ 1,1},{ 1,2},
            { 2,-1},{ 2,0},{ 2,1}
};

__global__ void k_bin(const float* __restrict__ pts, const float* __restrict__ intr) {
    int i = blockIdx.x * blockDim.x + threadIdx.x;
    if (i >= NPTS) return;
    float x = pts[3 * i + 0];
    float y = pts[3 * i + 1];
    float z = pts[3 * i + 2];
    if (z <= 1e-6f) return;                    // FAR point: never within radius
    float u = x * intr[0] / z + intr[2];       // same op order as reference
    float v = y * intr[4] / z + intr[5];
    int cu = min(max((int)floorf(u), 0), IMW - 1);
    int cv = min(max((int)floorf(v), 0), IMH - 1);
    int c = cv * IMW + cu;
    int pos = atomicAdd(&g_cnt[c], 1);
    if (pos < CAP) g_bin[c * CAP + pos] = make_float4(u, v, z, __int_as_float(i));
}

// 1 warp per pixel. Lane l walks cell l (21-cell window). Selected (wk,id)
// zero-padded to 16 slots; accumulation processes 2 candidates/iter with
// float4 feat loads, fully unrolled for maximum MLP.
__global__ void __launch_bounds__(256)
k_main(const float* __restrict__ colors, const float* __restrict__ feats,
       float* __restrict__ out) {
    __shared__ float  s_d2[8][MAXC];
    __shared__ float  s_z [8][MAXC];
    __shared__ float2 s_wi[8][MAXC];   // (wk, id-bits)

    int gt = blockIdx.x * blockDim.x + threadIdx.x;
    int p = gt >> 5;
    int lane = gt & 31;
    int w8 = (threadIdx.x >> 5);
    if (p >= HW) return;

    int pi = p >> 7, pj = p & 127;
    float uc = (float)pj + 0.5f;
    float vc = (float)pi + 0.5f;
    unsigned lt = (1u << lane) - 1u;

    // lane -> cell mapping
    int cnt_l = 0, base_l = 0;
    if (lane < NOFF) {
        int r = pi + c_off[lane][0];
        int c = pj + c_off[lane][1];
        if (r >= 0 && r < IMH && c >= 0 && c < IMW) {
            int cell = r * IMW + c;
            cnt_l = min(g_cnt[cell], CAP);
            base_l = cell * CAP;
        }
    }
    int maxc = cnt_l;
#pragma unroll
    for (int off = 16; off >= 1; off >>= 1)
        maxc = max(maxc, __shfl_xor_sync(FULL, maxc, off));

    // walk own cell; ballot-compact in-radius candidates into smem
    int nval = 0;
    float lsum = 0.0f, ldep = 0.0f;
#pragma unroll 1
    for (int j = 0; j < maxc; j++) {
        bool valid = false;
        float d2 = 0.0f, wk = 0.0f, z = 0.0f;
        int id = 0;
        if (j < cnt_l) {
            float4 pt = g_bin[base_l + j];
            float du = pt.x - uc;
            float dv = pt.y - vc;
            d2 = du * du + dv * dv;
            if (d2 < 4.0f) {
                valid = true;
                wk = __expf(-d2);
                z  = pt.z;
                id = __float_as_int(pt.w);
            }
        }
        unsigned bal = __ballot_sync(FULL, valid);
        int rk = nval + __popc(bal & lt);
        if (valid && rk < MAXC) {
            s_d2[w8][rk] = d2;
            s_z [w8][rk] = z;
            s_wi[w8][rk] = make_float2(wk, __int_as_float(id));
            lsum += wk;
            ldep += wk * z;
        }
        nval += __popc(bal);
    }
    nval = min(nval, MAXC);
    __syncwarp();

    float wsum, dep;
    int cnt;

    if (nval <= KNN) {
        // ---- fast path: all candidates contribute ----
#pragma unroll
        for (int off = 16; off >= 1; off >>= 1) {
            lsum += __shfl_xor_sync(FULL, lsum, off);
            ldep += __shfl_xor_sync(FULL, ldep, off);
        }
        wsum = lsum; dep = ldep; cnt = nval;
        // zero-pad slots [nval, 16)
        if (lane >= nval && lane < KNN)
            s_wi[w8][lane] = make_float2(0.0f, __int_as_float(0));
        __syncwarp();
    } else {
        // ---- slow path: parallel rank selection of 16 smallest d2 ----
        bool own0 = lane < nval;
        bool own1 = lane + 32 < nval;
        float d20 = own0 ? s_d2[w8][lane] : 0.0f;
        float d21 = own1 ? s_d2[w8][lane + 32] : 0.0f;
        float2 wi0 = own0 ? s_wi[w8][lane] : make_float2(0.0f, 0.0f);
        float2 wi1 = own1 ? s_wi[w8][lane + 32] : make_float2(0.0f, 0.0f);
        float z0  = own0 ? s_z[w8][lane] : 0.0f;
        float z1  = own1 ? s_z[w8][lane + 32] : 0.0f;

        int r0 = 0, r1 = 0;
#pragma unroll 4
        for (int j = 0; j < nval; j++) {
            float dj = s_d2[w8][j];
            r0 += (dj < d20) || (dj == d20 && j < lane);
            r1 += (dj < d21) || (dj == d21 && j < lane + 32);
        }
        bool sel0 = own0 && r0 < KNN;
        bool sel1 = own1 && r1 < KNN;

        float ls = 0.0f, ld = 0.0f;
        if (sel0) { ls += wi0.x; ld += wi0.x * z0; }
        if (sel1) { ls += wi1.x; ld += wi1.x * z1; }
#pragma unroll
        for (int off = 16; off >= 1; off >>= 1) {
            ls += __shfl_xor_sync(FULL, ls, off);
            ld += __shfl_xor_sync(FULL, ld, off);
        }
        wsum = ls; dep = ld;

        unsigned b0 = __ballot_sync(FULL, sel0);
        unsigned b1 = __ballot_sync(FULL, sel1);
        __syncwarp();
        if (sel0) s_wi[w8][__popc(b0 & lt)] = wi0;
        if (sel1) s_wi[w8][__popc(b0) + __popc(b1 & lt)] = wi1;
        cnt = KNN;
        __syncwarp();
    }

    // ---- accumulation: 2 candidates/iter, float4 feat loads, full unroll ----
    int half = lane >> 4;        // 0: even candidates, 1: odd
    int hl   = lane & 15;        // position within half-warp
    float4 acc = make_float4(0.0f, 0.0f, 0.0f, 0.0f);
    float col = 0.0f;
#pragma unroll
    for (int t = 0; t < KNN / 2; t++) {
        int k = 2 * t + half;
        float2 wi = s_wi[w8][k];            // LDS.64 broadcast (2 addr groups)
        float wk = wi.x;
        int   id = __float_as_int(wi.y);
        const float4* row = (const float4*)(feats + (long)id * FDIM);
        float4 f = row[hl];                 // 16 lanes x 16B = full 256B row
        acc.x += wk * f.x;
        acc.y += wk * f.y;
        acc.z += wk * f.z;
        acc.w += wk * f.w;
        if (hl < 3) col += wk * colors[3 * id + hl];
    }
    // fold halves
    acc.x += __shfl_xor_sync(FULL, acc.x, 16);
    acc.y += __shfl_xor_sync(FULL, acc.y, 16);
    acc.z += __shfl_xor_sync(FULL, acc.z, 16);
    acc.w += __shfl_xor_sync(FULL, acc.w, 16);
    col   += __shfl_xor_sync(FULL, col, 16);

    float inv = 1.0f / (wsum + 1e-10f);
    if (lane == 0) {
        out[OFF_DEP + p]  = dep * inv;
        out[OFF_MASK + p] = (cnt > 0) ? 1.0f : 0.0f;
    }
    if (lane < 3) out[OFF_COL + 3 * p + lane] = col * inv;
    if (half == 0) {
        float4 o = make_float4(acc.x * inv, acc.y * inv, acc.z * inv, acc.w * inv);
        ((float4*)(out + OFF_FEAT + p * FDIM))[hl] = o;
    }
}

extern "C" void kernel_launch(void* const* d_in, const int* in_sizes, int n_in,
                              void* d_out, int out_size) {
    const float* pts    = (const float*)d_in[0];   // (N,3)
    const float* colors = (const float*)d_in[1];   // (N,3)
    const float* feats  = (const float*)d_in[2];   // (N,64)
    const float* intr   = (const float*)d_in[3];   // (3,3)
    float* out = (float*)d_out;

    void* cnt_addr = nullptr;
    cudaGetSymbolAddress(&cnt_addr, g_cnt);
    cudaMemsetAsync(cnt_addr, 0, NCELLS * sizeof(int), 0);

    k_bin  <<<NPTS / 128, 128>>>(pts, intr);
    k_main <<<(HW * 32) / 256, 256>>>(colors, feats, out);
}

// round 10
// speedup vs baseline: 2.6095x; 1.0042x over previous
#include <cuda_runtime.h>

#define IMW 128
#define IMH 128
#define HW 16384
#define NPTS 16384
#define NCELLS 16384
#define KNN 16
#define FDIM 64
#define CAP 24          // bin capacity per cell (Poisson(1); P(>24) ~ 1e-24)
#define NOFF 21         // 5x5 window minus 4 corners (min d2 = 4.5 > 4)
#define MAXC 48         // max candidates kept (Poisson(12.6); P(>48) ~ 1e-13)

// float32 output packing: depths | colors(HW*3) | feats(HW*64) | masks
#define OFF_DEP  0
#define OFF_COL  16384
#define OFF_FEAT 65536
#define OFF_MASK 1114112

#define FULL 0xFFFFFFFFu

// ---- scratch (device globals; no cudaMalloc allowed) ----
__device__ int    g_cnt[NCELLS];
__device__ float4 g_bin[NCELLS * CAP];

// relative (dr,dc) offsets of the 21 reachable cells
__constant__ signed char c_off[NOFF][2] = {
            {-2,-1},{-2,0},{-2,1},
    {-1,-2},{-1,-1},{-1,0},{-1,1},{-1,2},
    { 0,-2},{ 0,-1},{ 0,0},{ 0,1},{ 0,2},
    { 1,-2},{ 1,-1},{ 1,0},{ 1,1},{ 1,2},
            { 2,-1},{ 2,0},{ 2,1}
};

__global__ void k_bin(const float* __restrict__ pts, const float* __restrict__ intr) {
    int i = blockIdx.x * blockDim.x + threadIdx.x;
    if (i >= NPTS) return;
    float x = pts[3 * i + 0];
    float y = pts[3 * i + 1];
    float z = pts[3 * i + 2];
    if (z <= 1e-6f) return;                    // FAR point: never within radius
    float u = x * intr[0] / z + intr[2];       // same op order as reference
    float v = y * intr[4] / z + intr[5];
    int cu = min(max((int)floorf(u), 0), IMW - 1);
    int cv = min(max((int)floorf(v), 0), IMH - 1);
    int c = cv * IMW + cu;
    int pos = atomicAdd(&g_cnt[c], 1);
    if (pos < CAP) g_bin[c * CAP + pos] = make_float4(u, v, z, __int_as_float(i));
}

// 1 warp per pixel. Pass 1: each lane walks its own cell with NO warp
// collectives (loads pipeline freely), building a valid bitmask + partials.
// One warp scan, then pass 2 re-walks valid entries (L1 hits) to compact
// into smem. Fast path (<=16): sum-all. Slow path: parallel rank selection.
__global__ void __launch_bounds__(256)
k_main(const float* __restrict__ colors, const float* __restrict__ feats,
       float* __restrict__ out) {
    __shared__ float  s_d2[8][MAXC];
    __shared__ float  s_z [8][MAXC];
    __shared__ float2 s_wi[8][MAXC];   // (wk, id-bits)

    int gt = blockIdx.x * blockDim.x + threadIdx.x;
    int p = gt >> 5;
    int lane = gt & 31;
    int w8 = (threadIdx.x >> 5);
    if (p >= HW) return;

    int pi = p >> 7, pj = p & 127;
    float uc = (float)pj + 0.5f;
    float vc = (float)pi + 0.5f;

    // lane -> cell mapping
    int cnt_l = 0, base_l = 0;
    if (lane < NOFF) {
        int r = pi + c_off[lane][0];
        int c = pj + c_off[lane][1];
        if (r >= 0 && r < IMH && c >= 0 && c < IMW) {
            int cell = r * IMW + c;
            cnt_l = min(g_cnt[cell], CAP);
            base_l = cell * CAP;
        }
    }

    // ---- pass 1: sync-free walk of own cell; batched loads (MLP) ----
    unsigned vmask = 0;
    float lsum = 0.0f, ldep = 0.0f;
#pragma unroll 1
    for (int j0 = 0; j0 < cnt_l; j0 += 4) {
        float4 pt[4];
#pragma unroll
        for (int u = 0; u < 4; u++)
            if (j0 + u < cnt_l) pt[u] = g_bin[base_l + j0 + u];
#pragma unroll
        for (int u = 0; u < 4; u++) {
            if (j0 + u < cnt_l) {
                float du = pt[u].x - uc;
                float dv = pt[u].y - vc;
                float d2 = du * du + dv * dv;
                if (d2 < 4.0f) {
                    vmask |= 1u << (j0 + u);
                    float wk = __expf(-d2);
                    lsum += wk;
                    ldep += wk * pt[u].z;
                }
            }
        }
    }

    // ---- warp scan of per-lane valid counts -> slot bases ----
    int nv = __popc(vmask);
    int pre = nv;
#pragma unroll
    for (int off = 1; off < 32; off <<= 1) {
        int o = __shfl_up_sync(FULL, pre, off);
        if (lane >= off) pre += o;
    }
    int nval = __shfl_sync(FULL, pre, 31);
    int slot = pre - nv;                       // exclusive base for this lane
    nval = min(nval, MAXC);

    bool slow = nval > KNN;

    // ---- pass 2: re-walk valid entries (L1 hits), compact to smem ----
    {
        unsigned m = vmask;
        int s = slot;
        while (m && s < MAXC) {
            int j = __ffs(m) - 1;
            m &= m - 1;
            float4 pt = g_bin[base_l + j];     // L1 hit
            float du = pt.x - uc;
            float dv = pt.y - vc;
            float d2 = du * du + dv * dv;
            float wk = __expf(-d2);
            s_wi[w8][s] = make_float2(wk, pt.w);
            if (slow) { s_d2[w8][s] = d2; s_z[w8][s] = pt.z; }
            s++;
        }
    }
    __syncwarp();

    float wsum, dep;
    int cnt;
    unsigned lt = (1u << lane) - 1u;

    if (!slow) {
        // ---- fast path: all candidates contribute ----
#pragma unroll
        for (int off = 16; off >= 1; off >>= 1) {
            lsum += __shfl_xor_sync(FULL, lsum, off);
            ldep += __shfl_xor_sync(FULL, ldep, off);
        }
        wsum = lsum; dep = ldep; cnt = nval;
        if (lane >= nval && lane < KNN)
            s_wi[w8][lane] = make_float2(0.0f, __int_as_float(0));
        __syncwarp();
    } else {
        // ---- slow path: parallel rank selection of 16 smallest d2 ----
        bool own0 = lane < nval;
        bool own1 = lane + 32 < nval;
        float d20 = own0 ? s_d2[w8][lane] : 0.0f;
        float d21 = own1 ? s_d2[w8][lane + 32] : 0.0f;
        float2 wi0 = own0 ? s_wi[w8][lane] : make_float2(0.0f, 0.0f);
        float2 wi1 = own1 ? s_wi[w8][lane + 32] : make_float2(0.0f, 0.0f);
        float z0  = own0 ? s_z[w8][lane] : 0.0f;
        float z1  = own1 ? s_z[w8][lane + 32] : 0.0f;

        int r0 = 0, r1 = 0;
#pragma unroll 4
        for (int j = 0; j < nval; j++) {
            float dj = s_d2[w8][j];
            r0 += (dj < d20) || (dj == d20 && j < lane);
            r1 += (dj < d21) || (dj == d21 && j < lane + 32);
        }
        bool sel0 = own0 && r0 < KNN;
        bool sel1 = own1 && r1 < KNN;

        float ls = 0.0f, ld = 0.0f;
        if (sel0) { ls += wi0.x; ld += wi0.x * z0; }
        if (sel1) { ls += wi1.x; ld += wi1.x * z1; }
#pragma unroll
        for (int off = 16; off >= 1; off >>= 1) {
            ls += __shfl_xor_sync(FULL, ls, off);
            ld += __shfl_xor_sync(FULL, ld, off);
        }
        wsum = ls; dep = ld;

        unsigned b0 = __ballot_sync(FULL, sel0);
        unsigned b1 = __ballot_sync(FULL, sel1);
        __syncwarp();
        if (sel0) s_wi[w8][__popc(b0 & lt)] = wi0;
        if (sel1) s_wi[w8][__popc(b0) + __popc(b1 & lt)] = wi1;
        cnt = KNN;
        __syncwarp();
    }

    // ---- accumulation: 2 candidates/iter, float4 feat loads, full unroll ----
    int half = lane >> 4;
    int hl   = lane & 15;
    float4 acc = make_float4(0.0f, 0.0f, 0.0f, 0.0f);
    float col = 0.0f;
#pragma unroll
    for (int t = 0; t < KNN / 2; t++) {
        int k = 2 * t + half;
        float2 wi = s_wi[w8][k];
        float wk = wi.x;
        int   id = __float_as_int(wi.y);
        const float4* row = (const float4*)(feats + (long)id * FDIM);
        float4 f = row[hl];
        acc.x += wk * f.x;
        acc.y += wk * f.y;
        acc.z += wk * f.z;
        acc.w += wk * f.w;
        if (hl < 3) col += wk * colors[3 * id + hl];
    }
    acc.x += __shfl_xor_sync(FULL, acc.x, 16);
    acc.y += __shfl_xor_sync(FULL, acc.y, 16);
    acc.z += __shfl_xor_sync(FULL, acc.z, 16);
    acc.w += __shfl_xor_sync(FULL, acc.w, 16);
    col   += __shfl_xor_sync(FULL, col, 16);

    float inv = 1.0f / (wsum + 1e-10f);
    if (lane == 0) {
        out[OFF_DEP + p]  = dep * inv;
        out[OFF_MASK + p] = (cnt > 0) ? 1.0f : 0.0f;
    }
    if (lane < 3) out[OFF_COL + 3 * p + lane] = col * inv;
    if (half == 0) {
        float4 o = make_float4(acc.x * inv, acc.y * inv, acc.z * inv, acc.w * inv);
        ((float4*)(out + OFF_FEAT + p * FDIM))[hl] = o;
    }
}

extern "C" void kernel_launch(void* const* d_in, const int* in_sizes, int n_in,
                              void* d_out, int out_size) {
    const float* pts    = (const float*)d_in[0];   // (N,3)
    const float* colors = (const float*)d_in[1];   // (N,3)
    const float* feats  = (const float*)d_in[2];   // (N,64)
    const float* intr   = (const float*)d_in[3];   // (3,3)
    float* out = (float*)d_out;

    void* cnt_addr = nullptr;
    cudaGetSymbolAddress(&cnt_addr, g_cnt);
    cudaMemsetAsync(cnt_addr, 0, NCELLS * sizeof(int), 0);

    k_bin  <<<NPTS / 128, 128>>>(pts, intr);
    k_main <<<(HW * 32) / 256, 256>>>(colors, feats, out);
}